// round 1
// baseline (speedup 1.0000x reference)
#include <cuda_runtime.h>

// RGCN, 2 layers, basis decomposition. Shapes fixed for this problem instance.
#define NN    100000   // nodes
#define RR    32       // relations
#define EE    3200000  // edges
#define EMBD  128      // embedding dim
#define HH    32       // hidden dim
#define BBASES 16      // num bases
#define CC    16       // output classes

// -------- scratch (static device globals; no allocation allowed) --------
__device__ float g_deg[RR * NN];                 // 12.8 MB  edge-count per (rel, fr)
__device__ float g_h1[NN * HH];                  // 12.8 MB  hidden1 accumulator (L2-resident)
__device__ float g_yb[NN * (BBASES * HH)];       // 204.8 MB yb[n][b*32+h] = emb @ bases1
__device__ float g_xw[RR * NN * HH];             // 409.6 MB xw[(r*N+n)*32+h]
__device__ float g_w2t[RR * CC * HH];            // 64 KB    w2 transposed to [r][c][h]

// -------- init: zero deg & hidden1, seed out with bias2 --------
__global__ void k_init(const float* __restrict__ bias2, float* __restrict__ out) {
    int i = blockIdx.x * blockDim.x + threadIdx.x;
    int stride = gridDim.x * blockDim.x;
    for (int idx = i; idx < RR * NN; idx += stride) g_deg[idx] = 0.f;
    for (int idx = i; idx < NN * HH; idx += stride) g_h1[idx] = 0.f;
    for (int idx = i; idx < NN * CC; idx += stride) out[idx] = bias2[idx & (CC - 1)];
}

// -------- w2t[r][c][h] = sum_b comps2[r,b] * bases2[b,h,c] --------
__global__ void k_w2t(const float* __restrict__ comps2, const float* __restrict__ bases2) {
    int idx = blockIdx.x * blockDim.x + threadIdx.x;
    if (idx >= RR * CC * HH) return;
    int r = idx >> 9;              // / (CC*HH)
    int c = (idx >> 5) & (CC - 1);
    int h = idx & (HH - 1);
    float acc = 0.f;
    #pragma unroll
    for (int b = 0; b < BBASES; b++)
        acc += comps2[r * BBASES + b] * bases2[(b * HH + h) * CC + c];
    g_w2t[idx] = acc;
}

// -------- deg[rel*N + fr] += 1 per edge --------
__global__ void k_deg(const int* __restrict__ rel, const int* __restrict__ fr) {
    int i = blockIdx.x * blockDim.x + threadIdx.x;
    int stride = gridDim.x * blockDim.x;
    for (int e = i; e < EE; e += stride)
        atomicAdd(&g_deg[rel[e] * NN + fr[e]], 1.0f);
}

// -------- GEMM: yb[n][j] = sum_k emb[n][k] * W[k][j],  W[k][b*32+h] = bases1[b][k][h]
#define BM 64
#define BN 64
#define BK 16
__global__ void k_gemm1(const float* __restrict__ A, const float* __restrict__ bases1) {
    __shared__ float As[BK][BM];   // A tile, transposed: As[k][m]
    __shared__ float Bs[BK][BN];
    int m0 = blockIdx.y * BM;
    int n0 = blockIdx.x * BN;
    int tid = threadIdx.x;
    int tx = tid & 15;
    int ty = tid >> 4;
    int arow = tid >> 2;           // 0..63
    int acol = (tid & 3) << 2;     // 0,4,8,12
    int brow = tid >> 4;           // 0..15
    int bcol = (tid & 15) << 2;    // 0..60
    int j  = n0 + bcol;
    int bb = j >> 5;               // basis index
    int hh = j & 31;               // h index
    const float* bsrc = bases1 + bb * (EMBD * HH) + hh;

    float acc[4][4] = {};
    for (int k0 = 0; k0 < EMBD; k0 += BK) {
        float4 av = make_float4(0.f, 0.f, 0.f, 0.f);
        int m = m0 + arow;
        if (m < NN) av = *(const float4*)(A + m * EMBD + k0 + acol);
        As[acol + 0][arow] = av.x;
        As[acol + 1][arow] = av.y;
        As[acol + 2][arow] = av.z;
        As[acol + 3][arow] = av.w;
        float4 bv = *(const float4*)(bsrc + (k0 + brow) * HH);
        *(float4*)&Bs[brow][bcol] = bv;
        __syncthreads();
        #pragma unroll
        for (int kk = 0; kk < BK; kk++) {
            float4 a = *(const float4*)&As[kk][ty << 2];
            float4 b = *(const float4*)&Bs[kk][tx << 2];
            acc[0][0] += a.x * b.x; acc[0][1] += a.x * b.y; acc[0][2] += a.x * b.z; acc[0][3] += a.x * b.w;
            acc[1][0] += a.y * b.x; acc[1][1] += a.y * b.y; acc[1][2] += a.y * b.z; acc[1][3] += a.y * b.w;
            acc[2][0] += a.z * b.x; acc[2][1] += a.z * b.y; acc[2][2] += a.z * b.z; acc[2][3] += a.z * b.w;
            acc[3][0] += a.w * b.x; acc[3][1] += a.w * b.y; acc[3][2] += a.w * b.z; acc[3][3] += a.w * b.w;
        }
        __syncthreads();
    }
    #pragma unroll
    for (int i = 0; i < 4; i++) {
        int m = m0 + (ty << 2) + i;
        if (m < NN)
            *(float4*)&g_yb[m * (BBASES * HH) + n0 + (tx << 2)] =
                make_float4(acc[i][0], acc[i][1], acc[i][2], acc[i][3]);
    }
}

// -------- combine: xw[(r*N+n)*32+h] = sum_b comps1[r,b] * yb[n][b*32+h] --------
__global__ void k_combine(const float* __restrict__ comps1) {
    __shared__ float syb[BBASES * HH];   // 512: one node's yb row
    __shared__ float sc1[RR * BBASES];   // 512: comps1
    int n = blockIdx.x;
    int tid = threadIdx.x;
    syb[tid]       = g_yb[n * 512 + tid];
    syb[tid + 256] = g_yb[n * 512 + tid + 256];
    sc1[tid]       = comps1[tid];
    sc1[tid + 256] = comps1[tid + 256];
    __syncthreads();
    int h  = tid & 31;
    int rb = (tid >> 5) << 2;  // warp id * 4: each warp covers 4 relations
    float a0 = 0.f, a1 = 0.f, a2 = 0.f, a3 = 0.f;
    #pragma unroll
    for (int b = 0; b < BBASES; b++) {
        float y = syb[b * HH + h];
        a0 += sc1[(rb + 0) * BBASES + b] * y;
        a1 += sc1[(rb + 1) * BBASES + b] * y;
        a2 += sc1[(rb + 2) * BBASES + b] * y;
        a3 += sc1[(rb + 3) * BBASES + b] * y;
    }
    g_xw[((rb + 0) * NN + n) * HH + h] = a0;
    g_xw[((rb + 1) * NN + n) * HH + h] = a1;
    g_xw[((rb + 2) * NN + n) * HH + h] = a2;
    g_xw[((rb + 3) * NN + n) * HH + h] = a3;
}

// -------- pass1: hidden1[fr] += val * xw[rel, to]   (warp per edge, lane = h) --------
__global__ void k_pass1(const int* __restrict__ rel, const int* __restrict__ fr,
                        const int* __restrict__ to) {
    int gid = blockIdx.x * blockDim.x + threadIdx.x;
    int lane = gid & 31;
    int warp = gid >> 5;
    int nwarps = (gridDim.x * blockDim.x) >> 5;
    for (int e = warp; e < EE; e += nwarps) {
        int r = rel[e], f = fr[e], t = to[e];
        float val = 1.0f / g_deg[r * NN + f];
        float x = g_xw[(r * NN + t) * HH + lane];
        atomicAdd(&g_h1[f * HH + lane], val * x);
    }
}

// -------- relu + bias1, in place --------
__global__ void k_relu(const float* __restrict__ bias1) {
    int i = blockIdx.x * blockDim.x + threadIdx.x;
    int stride = gridDim.x * blockDim.x;
    for (int idx = i; idx < NN * HH; idx += stride)
        g_h1[idx] = fmaxf(g_h1[idx] + bias1[idx & 31], 0.f);
}

// -------- pass2: out[fr] += val * (h1[to] @ w2[rel])  (16-lane group per edge, lane = c)
__global__ void k_pass2(const int* __restrict__ rel, const int* __restrict__ fr,
                        const int* __restrict__ to, float* __restrict__ out) {
    int gid = blockIdx.x * blockDim.x + threadIdx.x;
    int c = gid & 15;
    int grp = gid >> 4;
    int ngrp = (gridDim.x * blockDim.x) >> 4;
    for (int e = grp; e < EE; e += ngrp) {
        int r = rel[e], f = fr[e], t = to[e];
        float val = 1.0f / g_deg[r * NN + f];
        const float4* h1 = (const float4*)(g_h1 + t * HH);
        const float4* w2 = (const float4*)(g_w2t + (r * CC + c) * HH);
        float acc = 0.f;
        #pragma unroll
        for (int q = 0; q < HH / 4; q++) {
            float4 a = h1[q];
            float4 b = w2[q];
            acc += a.x * b.x + a.y * b.y + a.z * b.z + a.w * b.w;
        }
        atomicAdd(&out[f * CC + c], val * acc);
    }
}

extern "C" void kernel_launch(void* const* d_in, const int* in_sizes, int n_in,
                              void* d_out, int out_size) {
    const float* emb    = (const float*)d_in[0];
    const float* comps1 = (const float*)d_in[1];
    const float* bases1 = (const float*)d_in[2];
    const float* comps2 = (const float*)d_in[3];
    const float* bases2 = (const float*)d_in[4];
    const float* bias1  = (const float*)d_in[5];
    const float* bias2  = (const float*)d_in[6];
    const int*   rel    = (const int*)d_in[7];
    const int*   fr     = (const int*)d_in[8];
    const int*   to     = (const int*)d_in[9];
    float* out = (float*)d_out;

    k_init<<<12500, 256>>>(bias2, out);
    k_w2t<<<(RR * CC * HH + 255) / 256, 256>>>(comps2, bases2);
    k_deg<<<4096, 256>>>(rel, fr);
    k_gemm1<<<dim3((BBASES * HH) / BN, (NN + BM - 1) / BM), 256>>>(emb, bases1);
    k_combine<<<NN, 256>>>(comps1);
    k_pass1<<<4096, 256>>>(rel, fr, to);
    k_relu<<<12500, 256>>>(bias1);
    k_pass2<<<8192, 256>>>(rel, fr, to, out);
}

// round 2
// speedup vs baseline: 1.0546x; 1.0546x over previous
#include <cuda_runtime.h>

#define NN    100000   // nodes
#define RR    32       // relations
#define EE    3200000  // edges
#define EMBD  128      // embedding dim
#define HH    32       // hidden dim
#define BBASES 16      // num bases
#define CC    16       // output classes

// -------- scratch (static device globals) --------
__device__ float g_deg[RR * NN];                 // 12.8 MB  edge-count per (rel, fr)
__device__ float g_h1[NN * HH];                  // 12.8 MB  hidden1 accumulator (L2-resident)
__device__ float g_yb[NN * (BBASES * HH)];       // 204.8 MB yb[n][b*32+h] = emb @ bases1
__device__ float g_w2t[RR * CC * HH];            // 64 KB    w2 transposed to [r][c][h]
__device__ int   g_cnt[NN];                      // histogram of `to`
__device__ int   g_off[NN + 1];                  // group offsets (exclusive scan)
__device__ int   g_pos[NN];                      // running scatter positions
__device__ int   g_srt[EE];                      // sorted-by-to edges: packed rel*NN+fr

// -------- init: zero deg, hidden1, cnt; seed out with bias2 --------
__global__ void k_init(const float* __restrict__ bias2, float* __restrict__ out) {
    int i = blockIdx.x * blockDim.x + threadIdx.x;
    int stride = gridDim.x * blockDim.x;
    for (int idx = i; idx < RR * NN; idx += stride) g_deg[idx] = 0.f;
    for (int idx = i; idx < NN * HH; idx += stride) g_h1[idx] = 0.f;
    for (int idx = i; idx < NN; idx += stride) g_cnt[idx] = 0;
    for (int idx = i; idx < NN * CC; idx += stride) out[idx] = bias2[idx & (CC - 1)];
}

// -------- w2t[r][c][h] = sum_b comps2[r,b] * bases2[b,h,c] --------
__global__ void k_w2t(const float* __restrict__ comps2, const float* __restrict__ bases2) {
    int idx = blockIdx.x * blockDim.x + threadIdx.x;
    if (idx >= RR * CC * HH) return;
    int r = idx >> 9;
    int c = (idx >> 5) & (CC - 1);
    int h = idx & (HH - 1);
    float acc = 0.f;
    #pragma unroll
    for (int b = 0; b < BBASES; b++)
        acc += comps2[r * BBASES + b] * bases2[(b * HH + h) * CC + c];
    g_w2t[idx] = acc;
}

// -------- deg[rel*N + fr] += 1 per edge; also histogram `to` --------
__global__ void k_deg(const int* __restrict__ rel, const int* __restrict__ fr,
                      const int* __restrict__ to) {
    int i = blockIdx.x * blockDim.x + threadIdx.x;
    int stride = gridDim.x * blockDim.x;
    for (int e = i; e < EE; e += stride) {
        atomicAdd(&g_deg[rel[e] * NN + fr[e]], 1.0f);
        atomicAdd(&g_cnt[to[e]], 1);
    }
}

// -------- single-block exclusive scan of g_cnt -> g_off, g_pos --------
__global__ void k_scan() {
    __shared__ int s[1024];
    __shared__ int carry;
    if (threadIdx.x == 0) carry = 0;
    __syncthreads();
    for (int base = 0; base < NN; base += 1024) {
        int i = base + threadIdx.x;
        int v = (i < NN) ? g_cnt[i] : 0;
        s[threadIdx.x] = v;
        __syncthreads();
        #pragma unroll
        for (int d = 1; d < 1024; d <<= 1) {
            int t = (threadIdx.x >= d) ? s[threadIdx.x - d] : 0;
            __syncthreads();
            s[threadIdx.x] += t;
            __syncthreads();
        }
        int excl = s[threadIdx.x] - v;
        if (i < NN) { g_off[i] = carry + excl; g_pos[i] = carry + excl; }
        __syncthreads();
        if (threadIdx.x == 1023) carry += s[1023];
        __syncthreads();
    }
    if (threadIdx.x == 0) g_off[NN] = EE;
}

// -------- scatter edges into to-sorted order; record packs rel*NN+fr --------
__global__ void k_scatter(const int* __restrict__ rel, const int* __restrict__ fr,
                          const int* __restrict__ to) {
    int i = blockIdx.x * blockDim.x + threadIdx.x;
    int stride = gridDim.x * blockDim.x;
    for (int e = i; e < EE; e += stride) {
        int pos = atomicAdd(&g_pos[to[e]], 1);
        g_srt[pos] = rel[e] * NN + fr[e];
    }
}

// -------- GEMM: yb[n][j] = sum_k emb[n][k] * W[k][j],  W[k][b*32+h] = bases1[b][k][h]
#define BM 64
#define BN 64
#define BK 16
__global__ void k_gemm1(const float* __restrict__ A, const float* __restrict__ bases1) {
    __shared__ float As[BK][BM];
    __shared__ float Bs[BK][BN];
    int m0 = blockIdx.y * BM;
    int n0 = blockIdx.x * BN;
    int tid = threadIdx.x;
    int tx = tid & 15;
    int ty = tid >> 4;
    int arow = tid >> 2;
    int acol = (tid & 3) << 2;
    int brow = tid >> 4;
    int bcol = (tid & 15) << 2;
    int j  = n0 + bcol;
    int bb = j >> 5;
    int hh = j & 31;
    const float* bsrc = bases1 + bb * (EMBD * HH) + hh;

    float acc[4][4] = {};
    for (int k0 = 0; k0 < EMBD; k0 += BK) {
        float4 av = make_float4(0.f, 0.f, 0.f, 0.f);
        int m = m0 + arow;
        if (m < NN) av = *(const float4*)(A + m * EMBD + k0 + acol);
        As[acol + 0][arow] = av.x;
        As[acol + 1][arow] = av.y;
        As[acol + 2][arow] = av.z;
        As[acol + 3][arow] = av.w;
        float4 bv = *(const float4*)(bsrc + (k0 + brow) * HH);
        *(float4*)&Bs[brow][bcol] = bv;
        __syncthreads();
        #pragma unroll
        for (int kk = 0; kk < BK; kk++) {
            float4 a = *(const float4*)&As[kk][ty << 2];
            float4 b = *(const float4*)&Bs[kk][tx << 2];
            acc[0][0] += a.x * b.x; acc[0][1] += a.x * b.y; acc[0][2] += a.x * b.z; acc[0][3] += a.x * b.w;
            acc[1][0] += a.y * b.x; acc[1][1] += a.y * b.y; acc[1][2] += a.y * b.z; acc[1][3] += a.y * b.w;
            acc[2][0] += a.z * b.x; acc[2][1] += a.z * b.y; acc[2][2] += a.z * b.z; acc[2][3] += a.z * b.w;
            acc[3][0] += a.w * b.x; acc[3][1] += a.w * b.y; acc[3][2] += a.w * b.z; acc[3][3] += a.w * b.w;
        }
        __syncthreads();
    }
    #pragma unroll
    for (int i = 0; i < 4; i++) {
        int m = m0 + (ty << 2) + i;
        if (m < NN)
            *(float4*)&g_yb[m * (BBASES * HH) + n0 + (tx << 2)] =
                make_float4(acc[i][0], acc[i][1], acc[i][2], acc[i][3]);
    }
}

// -------- pass1 (sorted by to): block per node n; smem yb[n]; warp per edge --------
__global__ void k_pass1s(const float* __restrict__ comps1) {
    __shared__ float syb[BBASES * HH];   // 512: yb row of node n
    __shared__ float sc1[RR * BBASES];   // 512: comps1
    int n = blockIdx.x;
    int tid = threadIdx.x;               // 128 threads
    *(float4*)&syb[tid << 2] = *(const float4*)&g_yb[n * 512 + (tid << 2)];
    *(float4*)&sc1[tid << 2] = *(const float4*)&comps1[tid << 2];
    __syncthreads();
    int start = g_off[n], end = g_off[n + 1];
    int lane = tid & 31;
    int w = tid >> 5;
    for (int e = start + w; e < end; e += 4) {
        int rf = g_srt[e];
        int r = rf / NN;
        int f = rf - r * NN;
        float val = 1.0f / g_deg[rf];
        float acc = 0.f;
        #pragma unroll
        for (int b = 0; b < BBASES; b++)
            acc += sc1[r * BBASES + b] * syb[b * HH + lane];
        atomicAdd(&g_h1[f * HH + lane], val * acc);
    }
}

// -------- relu + bias1, in place --------
__global__ void k_relu(const float* __restrict__ bias1) {
    int i = blockIdx.x * blockDim.x + threadIdx.x;
    int stride = gridDim.x * blockDim.x;
    for (int idx = i; idx < NN * HH; idx += stride)
        g_h1[idx] = fmaxf(g_h1[idx] + bias1[idx & 31], 0.f);
}

// -------- pass2 (sorted by to): block per node n; smem h1[n]; 16-lane group per edge --
__global__ void k_pass2s(float* __restrict__ out) {
    __shared__ float sh1[HH];
    int n = blockIdx.x;
    int tid = threadIdx.x;               // 128 threads
    if (tid < HH) sh1[tid] = g_h1[n * HH + tid];
    __syncthreads();
    int c = tid & 15;
    int g = tid >> 4;                    // 8 groups
    int start = g_off[n], end = g_off[n + 1];
    for (int e = start + g; e < end; e += 8) {
        int rf = g_srt[e];
        int r = rf / NN;
        int f = rf - r * NN;
        float val = 1.0f / g_deg[rf];
        const float4* w2 = (const float4*)&g_w2t[(r * CC + c) * HH];
        const float4* h1 = (const float4*)sh1;
        float acc = 0.f;
        #pragma unroll
        for (int q = 0; q < HH / 4; q++) {
            float4 a = h1[q];
            float4 b = w2[q];
            acc += a.x * b.x + a.y * b.y + a.z * b.z + a.w * b.w;
        }
        atomicAdd(&out[f * CC + c], val * acc);
    }
}

extern "C" void kernel_launch(void* const* d_in, const int* in_sizes, int n_in,
                              void* d_out, int out_size) {
    const float* emb    = (const float*)d_in[0];
    const float* comps1 = (const float*)d_in[1];
    const float* bases1 = (const float*)d_in[2];
    const float* comps2 = (const float*)d_in[3];
    const float* bases2 = (const float*)d_in[4];
    const float* bias1  = (const float*)d_in[5];
    const float* bias2  = (const float*)d_in[6];
    const int*   rel    = (const int*)d_in[7];
    const int*   fr     = (const int*)d_in[8];
    const int*   to     = (const int*)d_in[9];
    float* out = (float*)d_out;

    k_init<<<12500, 256>>>(bias2, out);
    k_w2t<<<(RR * CC * HH + 255) / 256, 256>>>(comps2, bases2);
    k_deg<<<4096, 256>>>(rel, fr, to);
    k_scan<<<1, 1024>>>();
    k_scatter<<<4096, 256>>>(rel, fr, to);
    k_gemm1<<<dim3((BBASES * HH) / BN, (NN + BM - 1) / BM), 256>>>(emb, bases1);
    k_pass1s<<<NN, 128>>>(comps1);
    k_relu<<<12500, 256>>>(bias1);
    k_pass2s<<<NN, 128>>>(out);
}

// round 3
// speedup vs baseline: 1.1987x; 1.1367x over previous
#include <cuda_runtime.h>

#define NN    100000   // nodes
#define RR    32       // relations
#define EE    3200000  // edges
#define EMBD  128      // embedding dim
#define HH    32       // hidden dim
#define BBASES 16      // num bases
#define CC    16       // output classes

#define SCAN_BLOCKS ((NN + 1023) / 1024)   // 98

// -------- scratch (static device globals) --------
__device__ float g_deg[RR * NN];                 // 12.8 MB  edge-count per (rel, fr)
__device__ float g_h1[NN * HH];                  // 12.8 MB  hidden1 accumulator
__device__ float g_yb[NN * (BBASES * HH)];       // 204.8 MB yb[n][b*32+h] = emb @ bases1
__device__ float g_w2t[RR * CC * HH];            // 64 KB    w2 transposed to [r][c][h]
__device__ int   g_cnt[NN];                      // histogram of `to`
__device__ int   g_off[NN + 1];                  // group offsets (exclusive scan)
__device__ int   g_pos[NN];                      // running scatter positions
__device__ int   g_bsum[SCAN_BLOCKS];            // per-block scan totals
__device__ int2  g_ev[EE];                       // sorted edges: {(r<<17)|f, bits(val)}

// -------- init: zero deg, hidden1, cnt; seed out with bias2 --------
__global__ void k_init(const float* __restrict__ bias2, float* __restrict__ out) {
    int i = blockIdx.x * blockDim.x + threadIdx.x;
    int stride = gridDim.x * blockDim.x;
    for (int idx = i; idx < RR * NN; idx += stride) g_deg[idx] = 0.f;
    for (int idx = i; idx < NN * HH; idx += stride) g_h1[idx] = 0.f;
    for (int idx = i; idx < NN; idx += stride) g_cnt[idx] = 0;
    for (int idx = i; idx < NN * CC; idx += stride) out[idx] = bias2[idx & (CC - 1)];
}

// -------- w2t[r][c][h] = sum_b comps2[r,b] * bases2[b,h,c] --------
__global__ void k_w2t(const float* __restrict__ comps2, const float* __restrict__ bases2) {
    int idx = blockIdx.x * blockDim.x + threadIdx.x;
    if (idx >= RR * CC * HH) return;
    int r = idx >> 9;
    int c = (idx >> 5) & (CC - 1);
    int h = idx & (HH - 1);
    float acc = 0.f;
    #pragma unroll
    for (int b = 0; b < BBASES; b++)
        acc += comps2[r * BBASES + b] * bases2[(b * HH + h) * CC + c];
    g_w2t[idx] = acc;
}

// -------- deg[rel*N + fr] += 1 per edge; also histogram `to` --------
__global__ void k_deg(const int* __restrict__ rel, const int* __restrict__ fr,
                      const int* __restrict__ to) {
    int i = blockIdx.x * blockDim.x + threadIdx.x;
    int stride = gridDim.x * blockDim.x;
    for (int e = i; e < EE; e += stride) {
        atomicAdd(&g_deg[rel[e] * NN + fr[e]], 1.0f);
        atomicAdd(&g_cnt[to[e]], 1);
    }
}

// -------- multi-block exclusive scan: phase 1 (local scans + block sums) --------
__global__ void k_scan1() {
    __shared__ int s[1024];
    int tid = threadIdx.x;
    int i = blockIdx.x * 1024 + tid;
    int v = (i < NN) ? g_cnt[i] : 0;
    s[tid] = v;
    __syncthreads();
    #pragma unroll
    for (int d = 1; d < 1024; d <<= 1) {
        int t = (tid >= d) ? s[tid - d] : 0;
        __syncthreads();
        s[tid] += t;
        __syncthreads();
    }
    if (i < NN) g_off[i] = s[tid] - v;          // local exclusive
    if (tid == 1023) g_bsum[blockIdx.x] = s[1023];
}

// -------- scan phase 2: exclusive scan of the 98 block sums (1 block) --------
__global__ void k_scan2() {
    __shared__ int s[128];
    int tid = threadIdx.x;
    int v = (tid < SCAN_BLOCKS) ? g_bsum[tid] : 0;
    s[tid] = v;
    __syncthreads();
    #pragma unroll
    for (int d = 1; d < 128; d <<= 1) {
        int t = (tid >= d) ? s[tid - d] : 0;
        __syncthreads();
        s[tid] += t;
        __syncthreads();
    }
    if (tid < SCAN_BLOCKS) g_bsum[tid] = s[tid] - v;
}

// -------- scan phase 3: add carries, init g_pos --------
__global__ void k_scan3() {
    int i = blockIdx.x * 1024 + threadIdx.x;
    if (i < NN) {
        int o = g_off[i] + g_bsum[i >> 10];
        g_off[i] = o;
        g_pos[i] = o;
    }
    if (i == 0) g_off[NN] = EE;
}

// -------- scatter: to-sorted edge records with precomputed val --------
__global__ void k_scatter(const int* __restrict__ rel, const int* __restrict__ fr,
                          const int* __restrict__ to) {
    int i = blockIdx.x * blockDim.x + threadIdx.x;
    int stride = gridDim.x * blockDim.x;
    for (int e = i; e < EE; e += stride) {
        int r = rel[e], f = fr[e];
        int pos = atomicAdd(&g_pos[to[e]], 1);
        float val = 1.0f / g_deg[r * NN + f];
        g_ev[pos] = make_int2((r << 17) | f, __float_as_int(val));
    }
}

// -------- GEMM: yb[n][j] = sum_k emb[n][k] * W[k][j],  W[k][b*32+h] = bases1[b][k][h]
#define BM 64
#define BN 64
#define BK 16
__global__ void k_gemm1(const float* __restrict__ A, const float* __restrict__ bases1) {
    __shared__ float As[BK][BM];
    __shared__ float Bs[BK][BN];
    int m0 = blockIdx.y * BM;
    int n0 = blockIdx.x * BN;
    int tid = threadIdx.x;
    int tx = tid & 15;
    int ty = tid >> 4;
    int arow = tid >> 2;
    int acol = (tid & 3) << 2;
    int brow = tid >> 4;
    int bcol = (tid & 15) << 2;
    int j  = n0 + bcol;
    int bb = j >> 5;
    int hh = j & 31;
    const float* bsrc = bases1 + bb * (EMBD * HH) + hh;

    float acc[4][4] = {};
    for (int k0 = 0; k0 < EMBD; k0 += BK) {
        float4 av = make_float4(0.f, 0.f, 0.f, 0.f);
        int m = m0 + arow;
        if (m < NN) av = *(const float4*)(A + m * EMBD + k0 + acol);
        As[acol + 0][arow] = av.x;
        As[acol + 1][arow] = av.y;
        As[acol + 2][arow] = av.z;
        As[acol + 3][arow] = av.w;
        float4 bv = *(const float4*)(bsrc + (k0 + brow) * HH);
        *(float4*)&Bs[brow][bcol] = bv;
        __syncthreads();
        #pragma unroll
        for (int kk = 0; kk < BK; kk++) {
            float4 a = *(const float4*)&As[kk][ty << 2];
            float4 b = *(const float4*)&Bs[kk][tx << 2];
            acc[0][0] += a.x * b.x; acc[0][1] += a.x * b.y; acc[0][2] += a.x * b.z; acc[0][3] += a.x * b.w;
            acc[1][0] += a.y * b.x; acc[1][1] += a.y * b.y; acc[1][2] += a.y * b.z; acc[1][3] += a.y * b.w;
            acc[2][0] += a.z * b.x; acc[2][1] += a.z * b.y; acc[2][2] += a.z * b.z; acc[2][3] += a.z * b.w;
            acc[3][0] += a.w * b.x; acc[3][1] += a.w * b.y; acc[3][2] += a.w * b.z; acc[3][3] += a.w * b.w;
        }
        __syncthreads();
    }
    #pragma unroll
    for (int i = 0; i < 4; i++) {
        int m = m0 + (ty << 2) + i;
        if (m < NN)
            *(float4*)&g_yb[m * (BBASES * HH) + n0 + (tx << 2)] =
                make_float4(acc[i][0], acc[i][1], acc[i][2], acc[i][3]);
    }
}

__device__ __forceinline__ void red_add_v4(float* addr, float a, float b, float c, float d) {
    asm volatile("red.global.add.v4.f32 [%0], {%1, %2, %3, %4};"
                 :: "l"(addr), "f"(a), "f"(b), "f"(c), "f"(d) : "memory");
}

// -------- pass1 (sorted by to): block per node n; 4 edges/warp, lane = 4 h's --------
__global__ void k_pass1s(const float* __restrict__ comps1) {
    __shared__ float syb[BBASES * HH];   // 512: yb row of node n
    __shared__ float sc1[RR * BBASES];   // 512: comps1
    int n = blockIdx.x;
    int tid = threadIdx.x;               // 128 threads
    *(float4*)&syb[tid << 2] = *(const float4*)&g_yb[n * 512 + (tid << 2)];
    *(float4*)&sc1[tid << 2] = *(const float4*)&comps1[tid << 2];
    __syncthreads();
    int start = g_off[n], end = g_off[n + 1];
    int lane = tid & 31;
    int w = tid >> 5;
    int sub = lane >> 3;                 // 0..3: which edge in the quad
    int h4 = (lane & 7) << 2;            // h base: 0,4,...,28
    for (int base = start + (w << 2); base < end; base += 16) {
        int e = base + sub;
        if (e < end) {
            int2 ev = g_ev[e];
            int r = ev.x >> 17;
            int f = ev.x & 0x1FFFF;
            float val = __int_as_float(ev.y);
            float a0 = 0.f, a1 = 0.f, a2 = 0.f, a3 = 0.f;
            #pragma unroll
            for (int b = 0; b < BBASES; b++) {
                float c = sc1[r * BBASES + b];
                float4 y = *(const float4*)&syb[b * HH + h4];
                a0 += c * y.x; a1 += c * y.y; a2 += c * y.z; a3 += c * y.w;
            }
            red_add_v4(&g_h1[f * HH + h4], val * a0, val * a1, val * a2, val * a3);
        }
    }
}

// -------- pass2 (sorted by to): block per node; relu fused; 8 edges/warp, lane = 4 c's
__global__ void k_pass2s(const float* __restrict__ bias1, float* __restrict__ out) {
    __shared__ float sh1[HH];
    int n = blockIdx.x;
    int tid = threadIdx.x;               // 128 threads
    if (tid < HH) sh1[tid] = fmaxf(g_h1[n * HH + tid] + bias1[tid], 0.f);
    __syncthreads();
    // hoist h1 row into registers
    float4 hv[8];
    #pragma unroll
    for (int q = 0; q < 8; q++) hv[q] = *(const float4*)&sh1[q << 2];

    int start = g_off[n], end = g_off[n + 1];
    int lane = tid & 31;
    int w = tid >> 5;
    int sub = lane >> 2;                 // 0..7: which edge in the octet
    int c0 = (lane & 3) << 2;            // c base: 0,4,8,12
    for (int base = start + (w << 3); base < end; base += 32) {
        int e = base + sub;
        if (e < end) {
            int2 ev = g_ev[e];
            int r = ev.x >> 17;
            int f = ev.x & 0x1FFFF;
            float val = __int_as_float(ev.y);
            const float4* w2 = (const float4*)&g_w2t[(r * CC + c0) * HH];
            float acc[4];
            #pragma unroll
            for (int c = 0; c < 4; c++) {
                float s = 0.f;
                #pragma unroll
                for (int q = 0; q < 8; q++) {
                    float4 b = w2[c * 8 + q];
                    float4 a = hv[q];
                    s += a.x * b.x + a.y * b.y + a.z * b.z + a.w * b.w;
                }
                acc[c] = s * val;
            }
            red_add_v4(&out[f * CC + c0], acc[0], acc[1], acc[2], acc[3]);
        }
    }
}

extern "C" void kernel_launch(void* const* d_in, const int* in_sizes, int n_in,
                              void* d_out, int out_size) {
    const float* emb    = (const float*)d_in[0];
    const float* comps1 = (const float*)d_in[1];
    const float* bases1 = (const float*)d_in[2];
    const float* comps2 = (const float*)d_in[3];
    const float* bases2 = (const float*)d_in[4];
    const float* bias1  = (const float*)d_in[5];
    const float* bias2  = (const float*)d_in[6];
    const int*   rel    = (const int*)d_in[7];
    const int*   fr     = (const int*)d_in[8];
    const int*   to     = (const int*)d_in[9];
    float* out = (float*)d_out;

    k_init<<<12500, 256>>>(bias2, out);
    k_w2t<<<(RR * CC * HH + 255) / 256, 256>>>(comps2, bases2);
    k_deg<<<4096, 256>>>(rel, fr, to);
    k_scan1<<<SCAN_BLOCKS, 1024>>>();
    k_scan2<<<1, 128>>>();
    k_scan3<<<SCAN_BLOCKS, 1024>>>();
    k_scatter<<<4096, 256>>>(rel, fr, to);
    k_gemm1<<<dim3((BBASES * HH) / BN, (NN + BM - 1) / BM), 256>>>(emb, bases1);
    k_pass1s<<<NN, 128>>>(comps1);
    k_pass2s<<<NN, 128>>>(bias1, out);
}